// round 2
// baseline (speedup 1.0000x reference)
#include <cuda_runtime.h>
#include <math.h>

// ---------------- problem constants ----------------
constexpr int NH = 16, DH = 64, DM = 1024;
constexpr int QL = 1024, ML = 1024, KL = 2048, BS = 4;

// ---------------- f32x2 packed helpers ----------------
using u64 = unsigned long long;
__device__ __forceinline__ u64 f2fma(u64 a, u64 b, u64 c) {
    u64 d; asm("fma.rn.f32x2 %0, %1, %2, %3;" : "=l"(d) : "l"(a), "l"(b), "l"(c)); return d;
}
__device__ __forceinline__ u64 f2mul(u64 a, u64 b) {
    u64 d; asm("mul.rn.f32x2 %0, %1, %2;" : "=l"(d) : "l"(a), "l"(b)); return d;
}
__device__ __forceinline__ u64 f2add(u64 a, u64 b) {
    u64 d; asm("add.rn.f32x2 %0, %1, %2;" : "=l"(d) : "l"(a), "l"(b)); return d;
}
__device__ __forceinline__ u64 f2pack(float x, float y) {
    u64 d; asm("mov.b64 %0, {%1, %2};" : "=l"(d) : "f"(x), "f"(y)); return d;
}
__device__ __forceinline__ void f2unpack(u64 d, float& x, float& y) {
    asm("mov.b64 {%0, %1}, %2;" : "=f"(x), "=f"(y) : "l"(d));
}

// ---------------- scratch (device globals; no allocation) ----------------
__device__ float g_Qw[(size_t)BS*NH*QL*DH];   // (q + r_w_bias) * 0.125, [b][n][i][d]
__device__ float g_K [(size_t)BS*NH*KL*DH];   // [b][n][j][d]
__device__ float g_V [(size_t)BS*NH*KL*DH];   // [b][n][j][d]
__device__ float g_R [(size_t)NH*KL*DH];      // [n][j][d]
__device__ float g_brr[(size_t)NH*KL];        // (rr-rw)*0.125 . R[n][rel]
__device__ float g_av[(size_t)QL*BS*DM];      // attn_vec rows m = i*4+b
__device__ float g_tmp[(size_t)QL*BS*DM];     // w + attn_out (pre-LN)

// ---------------- generic tile params ----------------
constexpr int BM = 128, BN = 64, BK = 16;
constexpr int BDS = 2 * BN + 4;   // duplicated-B row stride (floats)

// ============ Kernel A: QKV projection (cat @ qkv_w^T) with scatter ============
__global__ void __launch_bounds__(256) qkv_kernel(const float* __restrict__ mems,
                                                  const float* __restrict__ w,
                                                  const float* __restrict__ qkv_w,
                                                  const float* __restrict__ rw_b) {
    __shared__ __align__(16) float As[BK][BM + 4];
    __shared__ __align__(16) float Bd[BK][BDS];
    const int bm = blockIdx.y * BM;       // over M = 8192 (m = k2*4 + b)
    const int bn = blockIdx.x * BN;       // over N = 3072
    const int t = threadIdx.x;
    const int tx = t & 15, ty = t >> 4;

    u64 acc2[4][4];
#pragma unroll
    for (int p = 0; p < 4; p++)
#pragma unroll
        for (int j = 0; j < 4; j++) acc2[p][j] = 0ull;

    for (int k0 = 0; k0 < DM; k0 += BK) {
#pragma unroll
        for (int u = 0; u < 2; u++) {
            int g = t + u * 256;                   // 0..511
            int row = g >> 2, c4 = g & 3;
            int m = bm + row;
            const float* Arow = (m < 4096) ? (mems + (size_t)m * DM)
                                           : (w + (size_t)(m - 4096) * DM);
            float4 v = *(const float4*)(Arow + k0 + c4 * 4);
            As[c4 * 4 + 0][row] = v.x; As[c4 * 4 + 1][row] = v.y;
            As[c4 * 4 + 2][row] = v.z; As[c4 * 4 + 3][row] = v.w;
        }
        {
            int row = t >> 2, c4 = t & 3;          // row = out-col in tile
            float4 v = *(const float4*)(qkv_w + (size_t)(bn + row) * DM + k0 + c4 * 4);
            *(u64*)&Bd[c4 * 4 + 0][2 * row] = f2pack(v.x, v.x);
            *(u64*)&Bd[c4 * 4 + 1][2 * row] = f2pack(v.y, v.y);
            *(u64*)&Bd[c4 * 4 + 2][2 * row] = f2pack(v.z, v.z);
            *(u64*)&Bd[c4 * 4 + 3][2 * row] = f2pack(v.w, v.w);
        }
        __syncthreads();
#pragma unroll
        for (int k = 0; k < BK; k++) {
            ulonglong2 A0 = *(const ulonglong2*)&As[k][ty * 8];
            ulonglong2 A1 = *(const ulonglong2*)&As[k][ty * 8 + 4];
            ulonglong2 B0 = *(const ulonglong2*)&Bd[k][tx * 8];
            ulonglong2 B1 = *(const ulonglong2*)&Bd[k][tx * 8 + 4];
            u64 a[4] = {A0.x, A0.y, A1.x, A1.y};
            u64 bp[4] = {B0.x, B0.y, B1.x, B1.y};
#pragma unroll
            for (int p = 0; p < 4; p++)
#pragma unroll
                for (int j = 0; j < 4; j++) acc2[p][j] = f2fma(a[p], bp[j], acc2[p][j]);
        }
        __syncthreads();
    }
    // scatter epilogue
#pragma unroll
    for (int p = 0; p < 4; p++) {
#pragma unroll
        for (int jj = 0; jj < 4; jj++) {
            float vlo, vhi;
            f2unpack(acc2[p][jj], vlo, vhi);
            int oc = bn + tx * 4 + jj;
            int region = oc >> 10;
            int oo = oc & 1023;
            int n = oo >> 6, d = oo & 63;
#pragma unroll
            for (int h = 0; h < 2; h++) {
                int m = bm + ty * 8 + 2 * p + h;
                int k2 = m >> 2, b = m & 3;
                float v = h ? vhi : vlo;
                if (region == 0) {
                    if (k2 >= ML) {
                        int i = k2 - ML;
                        g_Qw[((size_t)(b * NH + n) * QL + i) * DH + d] = (v + rw_b[oo]) * 0.125f;
                    }
                } else if (region == 1) {
                    g_K[((size_t)(b * NH + n) * KL + k2) * DH + d] = v;
                } else {
                    g_V[((size_t)(b * NH + n) * KL + k2) * DH + d] = v;
                }
            }
        }
    }
}

// ============ Kernel B: R projection (r @ r_net_w^T) with scatter ============
__global__ void __launch_bounds__(256) r_kernel(const float* __restrict__ r,
                                                const float* __restrict__ r_net_w) {
    __shared__ __align__(16) float As[BK][BM + 4];
    __shared__ __align__(16) float Bd[BK][BDS];
    const int bm = blockIdx.y * BM;       // over 2048
    const int bn = blockIdx.x * BN;       // over 1024
    const int t = threadIdx.x;
    const int tx = t & 15, ty = t >> 4;

    u64 acc2[4][4];
#pragma unroll
    for (int p = 0; p < 4; p++)
#pragma unroll
        for (int j = 0; j < 4; j++) acc2[p][j] = 0ull;

    for (int k0 = 0; k0 < DM; k0 += BK) {
#pragma unroll
        for (int u = 0; u < 2; u++) {
            int g = t + u * 256;
            int row = g >> 2, c4 = g & 3;
            float4 v = *(const float4*)(r + (size_t)(bm + row) * DM + k0 + c4 * 4);
            As[c4 * 4 + 0][row] = v.x; As[c4 * 4 + 1][row] = v.y;
            As[c4 * 4 + 2][row] = v.z; As[c4 * 4 + 3][row] = v.w;
        }
        {
            int row = t >> 2, c4 = t & 3;
            float4 v = *(const float4*)(r_net_w + (size_t)(bn + row) * DM + k0 + c4 * 4);
            *(u64*)&Bd[c4 * 4 + 0][2 * row] = f2pack(v.x, v.x);
            *(u64*)&Bd[c4 * 4 + 1][2 * row] = f2pack(v.y, v.y);
            *(u64*)&Bd[c4 * 4 + 2][2 * row] = f2pack(v.z, v.z);
            *(u64*)&Bd[c4 * 4 + 3][2 * row] = f2pack(v.w, v.w);
        }
        __syncthreads();
#pragma unroll
        for (int k = 0; k < BK; k++) {
            ulonglong2 A0 = *(const ulonglong2*)&As[k][ty * 8];
            ulonglong2 A1 = *(const ulonglong2*)&As[k][ty * 8 + 4];
            ulonglong2 B0 = *(const ulonglong2*)&Bd[k][tx * 8];
            ulonglong2 B1 = *(const ulonglong2*)&Bd[k][tx * 8 + 4];
            u64 a[4] = {A0.x, A0.y, A1.x, A1.y};
            u64 bp[4] = {B0.x, B0.y, B1.x, B1.y};
#pragma unroll
            for (int p = 0; p < 4; p++)
#pragma unroll
                for (int j = 0; j < 4; j++) acc2[p][j] = f2fma(a[p], bp[j], acc2[p][j]);
        }
        __syncthreads();
    }
#pragma unroll
    for (int p = 0; p < 4; p++) {
#pragma unroll
        for (int jj = 0; jj < 4; jj++) {
            float vlo, vhi;
            f2unpack(acc2[p][jj], vlo, vhi);
            int oc = bn + tx * 4 + jj;
            int n = oc >> 6, d = oc & 63;
            int j0r = bm + ty * 8 + 2 * p;
            g_R[((size_t)n * KL + j0r) * DH + d] = vlo;
            g_R[((size_t)n * KL + j0r + 1) * DH + d] = vhi;
        }
    }
}

// ============ Kernel B2: brr[n][rel] = ((rr-rw)*0.125) . R[n][rel] ============
__global__ void __launch_bounds__(256) brr_kernel(const float* __restrict__ rr_bias,
                                                  const float* __restrict__ rw_bias) {
    int idx = blockIdx.x * 256 + threadIdx.x;  // 0..NH*KL-1
    int n = idx >> 11, rel = idx & (KL - 1);
    const float4* Rp = (const float4*)(g_R + ((size_t)n * KL + rel) * DH);
    const float4* b1 = (const float4*)(rr_bias + n * DH);
    const float4* b2 = (const float4*)(rw_bias + n * DH);
    float acc = 0.f;
#pragma unroll
    for (int c = 0; c < 16; c++) {
        float4 rv = Rp[c]; float4 x = b1[c]; float4 y = b2[c];
        acc = fmaf((x.x - y.x) * 0.125f, rv.x, acc);
        acc = fmaf((x.y - y.y) * 0.125f, rv.y, acc);
        acc = fmaf((x.z - y.z) * 0.125f, rv.z, acc);
        acc = fmaf((x.w - y.w) * 0.125f, rv.w, acc);
    }
    g_brr[idx] = acc;
}

// ============ Kernel C: fused rel-attention (flash-style, f32x2) ============
constexpr int TI = 128, TJ = 16, RB = 144, RST = 68;

__global__ void __launch_bounds__(128) attn_kernel() {
    __shared__ __align__(16) float Ks[TJ * RST];
    __shared__ __align__(16) float Vs[TJ * RST];
    __shared__ __align__(16) float Rs[RB * RST];
    __shared__ float brr[RB];

    const int i0 = blockIdx.x * TI;
    const int b = blockIdx.y, n = blockIdx.z;
    const int t = threadIdx.x;

    const float* Qp = g_Qw + ((size_t)(b * NH + n) * QL + i0 + t) * DH;
    u64 q2[32];
#pragma unroll
    for (int c = 0; c < 16; c++) {
        ulonglong2 v = ((const ulonglong2*)Qp)[c];
        q2[2 * c] = v.x; q2[2 * c + 1] = v.y;
    }

    u64 o2[32];
#pragma unroll
    for (int c = 0; c < 32; c++) o2[c] = 0ull;
    float mrun = -1e30f, lrun = 0.f;

    const float* Kp = g_K + (size_t)(b * NH + n) * KL * DH;
    const float* Vp = g_V + (size_t)(b * NH + n) * KL * DH;
    const float* Rp = g_R + (size_t)n * KL * DH;
    const float* Bp = g_brr + (size_t)n * KL;

    const int i = i0 + t;
    const int jlim = i + ML;                              // inclusive
    const int jmax = min(KL, i0 + TI - 1 + ML + 1);       // exclusive (mult of 16)

    for (int j0 = 0; j0 < jmax; j0 += TJ) {
        __syncthreads();
#pragma unroll
        for (int u = 0; u < 2; u++) {
            int g = t + u * 128;
            int row = g >> 4, c4 = g & 15;
            ((float4*)Ks)[row * 17 + c4] = ((const float4*)(Kp + (size_t)(j0 + row) * DH))[c4];
            ((float4*)Vs)[row * 17 + c4] = ((const float4*)(Vp + (size_t)(j0 + row) * DH))[c4];
        }
        const int rel_base = j0 - i0 + 896;
#pragma unroll
        for (int u = 0; u < 18; u++) {
            int g = t + u * 128;
            int row = g >> 4, c4 = g & 15;
            int rel = rel_base + row;
            rel = (rel > KL - 1) ? (KL - 1) : rel;
            ((float4*)Rs)[row * 17 + c4] = ((const float4*)(Rp + (size_t)rel * DH))[c4];
        }
#pragma unroll
        for (int u = 0; u < 2; u++) {
            int row = t + u * 128;
            if (row < RB) {
                int rel = rel_base + row;
                rel = (rel > KL - 1) ? (KL - 1) : rel;
                brr[row] = Bp[rel];
            }
        }
        __syncthreads();

        float s[TJ];
#pragma unroll
        for (int rj = 0; rj < TJ; rj++) {
            const ulonglong2* kr = (const ulonglong2*)(Ks + rj * RST);
            const int row = rj + (TI - 1) - t;            // 0..142
            const ulonglong2* rr = (const ulonglong2*)(Rs + row * RST);
            u64 aK0 = 0ull, aK1 = 0ull, aR0 = 0ull, aR1 = 0ull;
#pragma unroll
            for (int c = 0; c < 16; c++) {
                ulonglong2 kk = kr[c];
                ulonglong2 rv = rr[c];
                aK0 = f2fma(q2[2 * c], kk.x, aK0);
                aK1 = f2fma(q2[2 * c + 1], kk.y, aK1);
                aR0 = f2fma(q2[2 * c], rv.x, aR0);
                aR1 = f2fma(q2[2 * c + 1], rv.y, aR1);
            }
            u64 sA = f2add(aK0, aK1);
            u64 sB = f2add(aR0, aR1);
            u64 sC = f2add(sA, sB);
            float x, y;
            f2unpack(sC, x, y);
            float sv = x + y + brr[row];
            s[rj] = (j0 + rj > jlim) ? -1e30f : sv;
        }
        float tmax = s[0];
#pragma unroll
        for (int rj = 1; rj < TJ; rj++) tmax = fmaxf(tmax, s[rj]);
        float mnew = fmaxf(mrun, tmax);
        float corr = __expf(mrun - mnew);
        lrun *= corr;
        u64 cp = f2pack(corr, corr);
#pragma unroll
        for (int c = 0; c < 32; c++) o2[c] = f2mul(o2[c], cp);
#pragma unroll
        for (int rj = 0; rj < TJ; rj++) {
            float p = __expf(s[rj] - mnew);
            lrun += p;
            u64 pp = f2pack(p, p);
            const ulonglong2* vr = (const ulonglong2*)(Vs + rj * RST);
#pragma unroll
            for (int c = 0; c < 16; c++) {
                ulonglong2 vv = vr[c];
                o2[2 * c] = f2fma(pp, vv.x, o2[2 * c]);
                o2[2 * c + 1] = f2fma(pp, vv.y, o2[2 * c + 1]);
            }
        }
        mrun = mnew;
    }

    const float inv = 1.f / lrun;
    u64 ip = f2pack(inv, inv);
    ulonglong2* op = (ulonglong2*)(g_av + (size_t)((i0 + t) * BS + b) * DM + n * DH);
#pragma unroll
    for (int c = 0; c < 16; c++) {
        ulonglong2 v;
        v.x = f2mul(o2[2 * c], ip);
        v.y = f2mul(o2[2 * c + 1], ip);
        op[c] = v;
    }
}

// ============ Kernel D: output projection + residual ============
__global__ void __launch_bounds__(256) o_kernel(const float* __restrict__ o_w,
                                                const float* __restrict__ w) {
    __shared__ __align__(16) float As[BK][BM + 4];
    __shared__ __align__(16) float Bd[BK][BDS];
    const int bm = blockIdx.y * BM;       // over 4096
    const int bn = blockIdx.x * BN;       // over 1024
    const int t = threadIdx.x;
    const int tx = t & 15, ty = t >> 4;

    u64 acc2[4][4];
#pragma unroll
    for (int p = 0; p < 4; p++)
#pragma unroll
        for (int j = 0; j < 4; j++) acc2[p][j] = 0ull;

    for (int k0 = 0; k0 < DM; k0 += BK) {
#pragma unroll
        for (int u = 0; u < 2; u++) {
            int g = t + u * 256;
            int row = g >> 2, c4 = g & 3;
            float4 v = *(const float4*)(g_av + (size_t)(bm + row) * DM + k0 + c4 * 4);
            As[c4 * 4 + 0][row] = v.x; As[c4 * 4 + 1][row] = v.y;
            As[c4 * 4 + 2][row] = v.z; As[c4 * 4 + 3][row] = v.w;
        }
        {
            int row = t >> 2, c4 = t & 3;
            float4 v = *(const float4*)(o_w + (size_t)(bn + row) * DM + k0 + c4 * 4);
            *(u64*)&Bd[c4 * 4 + 0][2 * row] = f2pack(v.x, v.x);
            *(u64*)&Bd[c4 * 4 + 1][2 * row] = f2pack(v.y, v.y);
            *(u64*)&Bd[c4 * 4 + 2][2 * row] = f2pack(v.z, v.z);
            *(u64*)&Bd[c4 * 4 + 3][2 * row] = f2pack(v.w, v.w);
        }
        __syncthreads();
#pragma unroll
        for (int k = 0; k < BK; k++) {
            ulonglong2 A0 = *(const ulonglong2*)&As[k][ty * 8];
            ulonglong2 A1 = *(const ulonglong2*)&As[k][ty * 8 + 4];
            ulonglong2 B0 = *(const ulonglong2*)&Bd[k][tx * 8];
            ulonglong2 B1 = *(const ulonglong2*)&Bd[k][tx * 8 + 4];
            u64 a[4] = {A0.x, A0.y, A1.x, A1.y};
            u64 bp[4] = {B0.x, B0.y, B1.x, B1.y};
#pragma unroll
            for (int p = 0; p < 4; p++)
#pragma unroll
                for (int j = 0; j < 4; j++) acc2[p][j] = f2fma(a[p], bp[j], acc2[p][j]);
        }
        __syncthreads();
    }
#pragma unroll
    for (int p = 0; p < 4; p++) {
#pragma unroll
        for (int jj = 0; jj < 4; jj++) {
            float vlo, vhi;
            f2unpack(acc2[p][jj], vlo, vhi);
            int oc = bn + tx * 4 + jj;
            int m0 = bm + ty * 8 + 2 * p;
            g_tmp[(size_t)m0 * DM + oc] = vlo + w[(size_t)m0 * DM + oc];
            g_tmp[(size_t)(m0 + 1) * DM + oc] = vhi + w[(size_t)(m0 + 1) * DM + oc];
        }
    }
}

// ============ Kernel E: LayerNorm ============
__global__ void __launch_bounds__(256) ln_kernel(const float* __restrict__ gamma,
                                                 const float* __restrict__ beta,
                                                 float* __restrict__ out) {
    const int row = blockIdx.x;
    const float* x = g_tmp + (size_t)row * DM;
    float s = 0.f, ss = 0.f;
#pragma unroll
    for (int u = 0; u < 4; u++) {
        float v = x[threadIdx.x + u * 256];
        s += v; ss += v * v;
    }
#pragma unroll
    for (int off = 16; off; off >>= 1) {
        s += __shfl_xor_sync(0xffffffffu, s, off);
        ss += __shfl_xor_sync(0xffffffffu, ss, off);
    }
    __shared__ float sm_s[8], sm_ss[8];
    int wid = threadIdx.x >> 5, lid = threadIdx.x & 31;
    if (lid == 0) { sm_s[wid] = s; sm_ss[wid] = ss; }
    __syncthreads();
    if (threadIdx.x == 0) {
        float a = 0.f, b2 = 0.f;
#pragma unroll
        for (int i2 = 0; i2 < 8; i2++) { a += sm_s[i2]; b2 += sm_ss[i2]; }
        sm_s[0] = a; sm_ss[0] = b2;
    }
    __syncthreads();
    const float mu = sm_s[0] * (1.f / DM);
    const float var = sm_ss[0] * (1.f / DM) - mu * mu;
    const float inv = rsqrtf(var + 1e-5f);
#pragma unroll
    for (int u = 0; u < 4; u++) {
        int c = threadIdx.x + u * 256;
        out[(size_t)row * DM + c] = (x[c] - mu) * inv * gamma[c] + beta[c];
    }
}

// ============ launch ============
extern "C" void kernel_launch(void* const* d_in, const int* in_sizes, int n_in,
                              void* d_out, int out_size) {
    const float* w       = (const float*)d_in[0];   // [1024,4,1024]
    const float* r       = (const float*)d_in[1];   // [2048,1024]
    const float* mems    = (const float*)d_in[2];   // [1024,4,1024]
    // d_in[3] = attn_mask  (unused; mask computed analytically: j > i + MLEN)
    const float* qkv_w   = (const float*)d_in[4];   // [3072,1024]
    const float* r_net_w = (const float*)d_in[5];   // [1024,1024]
    const float* o_w     = (const float*)d_in[6];   // [1024,1024]
    const float* rr_bias = (const float*)d_in[7];   // [16,64]
    const float* rw_bias = (const float*)d_in[8];   // [16,64]
    const float* ln_g    = (const float*)d_in[9];   // [1024]
    const float* ln_b    = (const float*)d_in[10];  // [1024]
    float* out = (float*)d_out;

    qkv_kernel<<<dim3(48, 64), 256>>>(mems, w, qkv_w, rw_bias);
    r_kernel<<<dim3(16, 16), 256>>>(r, r_net_w);
    brr_kernel<<<NH * KL / 256, 256>>>(rr_bias, rw_bias);
    attn_kernel<<<dim3(8, 4, 16), 128>>>();
    o_kernel<<<dim3(16, 32), 256>>>(o_w, w);
    ln_kernel<<<4096, 256>>>(ln_g, ln_b, out);
}

// round 4
// speedup vs baseline: 3.6856x; 3.6856x over previous
#include <cuda_runtime.h>
#include <cuda_fp16.h>
#include <math.h>
#include <cstdint>

// ---------------- problem constants ----------------
constexpr int NH = 16, DH = 64, DM = 1024;
constexpr int QL = 1024, ML = 1024, KL = 2048, BS = 4;

// ---------------- scratch (device globals; no allocation) ----------------
__device__ __half g_Ah [(size_t)8192 * 1024];   // fp16 cat rows (m = k2*4+b)
__device__ __half g_W3h[(size_t)3072 * 1024];   // fp16 qkv_w
__device__ __half g_Ph [(size_t)2048 * 1024];   // fp16 r input
__device__ __half g_Wrh[(size_t)1024 * 1024];   // fp16 r_net_w
__device__ __half g_Woh[(size_t)1024 * 1024];   // fp16 o_w
__device__ __half g_Qwh[(size_t)BS * NH * QL * DH];  // (q+rw_bias)*0.125  [b*16+n][i][d]
__device__ __half g_Kh [(size_t)BS * NH * KL * DH];  // [b*16+n][j][d]
__device__ __half g_Vt [(size_t)BS * NH * DH * KL];  // [b*16+n][d][j]  (transposed!)
__device__ __half g_Rh [(size_t)NH * KL * DH];       // [n][rel][d]
__device__ __half g_Th [(size_t)64 * QL * KL];       // T[z][i][rel] = Qw_i . R_rel
__device__ __half g_P  [(size_t)64 * QL * KL];       // softmax probs
__device__ __half g_avh[(size_t)QL * BS * DM];       // attn_vec rows m = i*4+b
__device__ float  g_S  [(size_t)64 * QL * KL];       // scores fp32
__device__ float  g_tmp[(size_t)QL * BS * DM];       // w + attn_out (pre-LN)
__device__ float  g_brr[NH * KL];                    // (rr-rw)*0.125 . R[n][rel]

// ---------------- PTX helpers ----------------
__device__ __forceinline__ uint32_t smem_u32(const void* p) {
    uint32_t a;
    asm("{ .reg .u64 t; cvta.to.shared.u64 t, %1; cvt.u32.u64 %0, t; }" : "=r"(a) : "l"(p));
    return a;
}
__device__ __forceinline__ void ldsm_x4(uint32_t& r0, uint32_t& r1, uint32_t& r2, uint32_t& r3,
                                        uint32_t addr) {
    asm volatile("ldmatrix.sync.aligned.m8n8.x4.shared.b16 {%0,%1,%2,%3}, [%4];"
                 : "=r"(r0), "=r"(r1), "=r"(r2), "=r"(r3) : "r"(addr));
}
__device__ __forceinline__ void mma16816(float* d, const uint32_t* a, const uint32_t* b) {
    asm volatile("mma.sync.aligned.m16n8k16.row.col.f32.f16.f16.f32 "
                 "{%0,%1,%2,%3}, {%4,%5,%6,%7}, {%8,%9}, {%0,%1,%2,%3};"
                 : "+f"(d[0]), "+f"(d[1]), "+f"(d[2]), "+f"(d[3])
                 : "r"(a[0]), "r"(a[1]), "r"(a[2]), "r"(a[3]), "r"(b[0]), "r"(b[1]));
}

// ============ fp32 -> fp16 conversion (SEL picks destination global) ============
template <int SEL>
__global__ void __launch_bounds__(256) conv_kernel(const float* __restrict__ src, int n4) {
    int i = blockIdx.x * 256 + threadIdx.x;
    if (i >= n4) return;
    __half* dst = (SEL == 0) ? g_Ah
                : (SEL == 1) ? g_Ah + (size_t)4096 * 1024
                : (SEL == 2) ? g_W3h
                : (SEL == 3) ? g_Ph
                : (SEL == 4) ? g_Wrh : g_Woh;
    float4 v = ((const float4*)src)[i];
    __half2* d2 = (__half2*)dst;
    d2[2 * i]     = __floats2half2_rn(v.x, v.y);
    d2[2 * i + 1] = __floats2half2_rn(v.z, v.w);
}

// ============ generic warp-tiled HMMA GEMM, D = A @ B^T (both k-major fp16) ============
// MODE 0: qkv   M=8192 N=3072 K=1024  -> scatter Qwh/Kh/Vt     (aux = rw_bias)
// MODE 1: r     M=2048 N=1024 K=1024  -> scatter Rh
// MODE 2: o     M=4096 N=1024 K=1024  -> g_tmp = D + aux(=w)
// MODE 3: T     M=1024 N=2048 K=64    batched z=64
// MODE 4: S(AC) M=1024 N=2048 K=64    batched, + T gather + brr + mask -> g_S
// MODE 5: PV    M=1024 N=64   K=2048  batched -> g_avh
template <int MODE>
__global__ void __launch_bounds__(256) gemm_mma(const float* __restrict__ aux) {
    constexpr int K       = (MODE <= 2) ? 1024 : (MODE <= 4) ? 64 : 2048;
    constexpr int BN      = (MODE == 5) ? 64 : 128;
    constexpr int WARPS_M = (MODE == 5) ? 4 : 2;
    constexpr int WARPS_N = 8 / WARPS_M;
    constexpr int WM = 128 / WARPS_M;          // 64 or 32
    constexpr int WN = BN / WARPS_N;           // 32
    constexpr int MT = WM / 16;                // 4 or 2
    constexpr int NT = WN / 8;                 // 4
    constexpr int LDS = 40;                    // halves (80B: conflict-free ldmatrix)
    constexpr int KC = K / 32;

    __shared__ __align__(16) __half As[2][128 * LDS];
    __shared__ __align__(16) __half Bs[2][BN * LDS];

    const int t = threadIdx.x, lane = t & 31, wid = t >> 5;
    const int wy = wid % WARPS_M, wx = wid / WARPS_M;
    const int bm = blockIdx.y * 128, bn = blockIdx.x * BN;
    const int z = blockIdx.z;

    const __half* Ab;
    const __half* Bb;
    if constexpr (MODE == 0)      { Ab = g_Ah;  Bb = g_W3h; }
    else if constexpr (MODE == 1) { Ab = g_Ph;  Bb = g_Wrh; }
    else if constexpr (MODE == 2) { Ab = g_avh; Bb = g_Woh; }
    else if constexpr (MODE == 3) { Ab = g_Qwh + (size_t)z * QL * DH; Bb = g_Rh + (size_t)(z & 15) * KL * DH; }
    else if constexpr (MODE == 4) { Ab = g_Qwh + (size_t)z * QL * DH; Bb = g_Kh + (size_t)z * KL * DH; }
    else                          { Ab = g_P + (size_t)z * QL * KL;   Bb = g_Vt + (size_t)z * DH * KL; }

    const int lrow = t >> 2, lc = (t & 3) * 8;       // 128 rows x 4 16B-chunks
    const __half* aS0 = Ab + (size_t)(bm + lrow) * K + lc;
    const __half* aS1 = Ab + (size_t)(bm + lrow + 64) * K + lc;
    const __half* bS0 = Bb + (size_t)(bn + lrow) * K + lc;
    const __half* bS1 = Bb + (size_t)(bn + ((BN == 128) ? lrow + 64 : lrow)) * K + lc;
    const int sA0 = lrow * LDS + lc, sA1 = (lrow + 64) * LDS + lc;

    // chunk 0 -> buffer 0
    *(uint4*)&As[0][sA0] = *(const uint4*)aS0;
    *(uint4*)&As[0][sA1] = *(const uint4*)aS1;
    *(uint4*)&Bs[0][sA0] = *(const uint4*)bS0;
    if (BN == 128) *(uint4*)&Bs[0][sA1] = *(const uint4*)bS1;
    __syncthreads();

    float D[MT][NT][4];
#pragma unroll
    for (int mt = 0; mt < MT; mt++)
#pragma unroll
        for (int nt = 0; nt < NT; nt++)
#pragma unroll
            for (int r = 0; r < 4; r++) D[mt][nt][r] = 0.f;

    for (int kc = 0; kc < KC; kc++) {
        const int cur = kc & 1;
        uint4 pa0 = {}, pa1 = {}, pb0 = {}, pb1 = {};
        const bool pf = (kc + 1 < KC);
        if (pf) {
            pa0 = *(const uint4*)(aS0 + (kc + 1) * 32);
            pa1 = *(const uint4*)(aS1 + (kc + 1) * 32);
            pb0 = *(const uint4*)(bS0 + (kc + 1) * 32);
            if (BN == 128) pb1 = *(const uint4*)(bS1 + (kc + 1) * 32);
        }
        const uint32_t smA = smem_u32(&As[cur][0]);
        const uint32_t smB = smem_u32(&Bs[cur][0]);
#pragma unroll
        for (int ks = 0; ks < 2; ks++) {
            uint32_t af[MT][4], bf[NT][2];
#pragma unroll
            for (int mt = 0; mt < MT; mt++) {
                uint32_t a = smA + 2 * ((wy * WM + mt * 16 + (lane & 15)) * LDS
                                        + ks * 16 + (lane >> 4) * 8);
                ldsm_x4(af[mt][0], af[mt][1], af[mt][2], af[mt][3], a);
            }
#pragma unroll
            for (int np = 0; np < NT / 2; np++) {
                uint32_t a = smB + 2 * ((wx * WN + np * 16 + (lane & 7) + ((lane >> 4) << 3)) * LDS
                                        + ks * 16 + ((lane >> 3) & 1) * 8);
                ldsm_x4(bf[2 * np][0], bf[2 * np][1], bf[2 * np + 1][0], bf[2 * np + 1][1], a);
            }
#pragma unroll
            for (int mt = 0; mt < MT; mt++)
#pragma unroll
                for (int nt = 0; nt < NT; nt++)
                    mma16816(D[mt][nt], af[mt], bf[nt]);
        }
        if (pf) {
            *(uint4*)&As[1 - cur][sA0] = pa0;
            *(uint4*)&As[1 - cur][sA1] = pa1;
            *(uint4*)&Bs[1 - cur][sA0] = pb0;
            if (BN == 128) *(uint4*)&Bs[1 - cur][sA1] = pb1;
            __syncthreads();
        }
    }

    // ---------------- epilogue ----------------
#pragma unroll
    for (int mt = 0; mt < MT; mt++) {
#pragma unroll
        for (int nt = 0; nt < NT; nt++) {
#pragma unroll
            for (int r = 0; r < 4; r++) {
                const int row = bm + wy * WM + mt * 16 + (lane >> 2) + ((r >> 1) << 3);
                const int col = bn + wx * WN + nt * 8 + ((lane & 3) << 1) + (r & 1);
                const float v = D[mt][nt][r];
                if constexpr (MODE == 0) {
                    const int k2 = row >> 2, b = row & 3;
                    const int region = col >> 10, oo = col & 1023;
                    const int n = oo >> 6, d = oo & 63;
                    if (region == 0) {
                        if (k2 >= ML)
                            g_Qwh[(((size_t)(b * NH + n)) * QL + (k2 - ML)) * DH + d] =
                                __float2half((v + aux[oo]) * 0.125f);
                    } else if (region == 1) {
                        g_Kh[(((size_t)(b * NH + n)) * KL + k2) * DH + d] = __float2half(v);
                    } else {
                        g_Vt[(((size_t)(b * NH + n)) * DH + d) * KL + k2] = __float2half(v);
                    }
                } else if constexpr (MODE == 1) {
                    g_Rh[(((size_t)(col >> 6)) * KL + row) * DH + (col & 63)] = __float2half(v);
                } else if constexpr (MODE == 2) {
                    g_tmp[(size_t)row * DM + col] = v + aux[(size_t)row * DM + col];
                } else if constexpr (MODE == 3) {
                    g_Th[((size_t)z * QL + row) * KL + col] = __float2half(v);
                } else if constexpr (MODE == 4) {
                    float sv = -1e30f;
                    if (col <= row + ML) {
                        const int rel = col - row + (QL - 1);
                        sv = v + __half2float(g_Th[((size_t)z * QL + row) * KL + rel])
                               + g_brr[(z & 15) * KL + rel];
                    }
                    g_S[((size_t)z * QL + row) * KL + col] = sv;
                } else {
                    g_avh[((size_t)row * BS + (z >> 4)) * DM + (z & 15) * DH + col] =
                        __float2half(v);
                }
            }
        }
    }
}

// ============ brr[n][rel] = ((rr-rw)*0.125) . R[n][rel] ============
__global__ void __launch_bounds__(256) brr_kernel(const float* __restrict__ rr_bias,
                                                  const float* __restrict__ rw_bias) {
    int idx = blockIdx.x * 256 + threadIdx.x;  // 0..NH*KL-1
    int n = idx >> 11, rel = idx & (KL - 1);
    const __half* Rp = g_Rh + ((size_t)n * KL + rel) * DH;
    float acc = 0.f;
#pragma unroll
    for (int c = 0; c < DH; c++)
        acc = fmaf((rr_bias[n * DH + c] - rw_bias[n * DH + c]) * 0.125f,
                   __half2float(Rp[c]), acc);
    g_brr[idx] = acc;
}

// ============ row softmax: S (fp32) -> P (fp16) ============
__global__ void __launch_bounds__(256) softmax_kernel() {
    const size_t row = blockIdx.x;
    const float* Sp = g_S + row * KL;
    __half* Pp = g_P + row * KL;
    const int t = threadIdx.x;
    const int wid = t >> 5, lid = t & 31;

    float v[8];
#pragma unroll
    for (int u = 0; u < 8; u++) v[u] = Sp[t + (u << 8)];

    float mx = v[0];
#pragma unroll
    for (int u = 1; u < 8; u++) mx = fmaxf(mx, v[u]);
#pragma unroll
    for (int off = 16; off; off >>= 1) mx = fmaxf(mx, __shfl_xor_sync(0xffffffffu, mx, off));
    __shared__ float smx[8], ssm[8];
    if (lid == 0) smx[wid] = mx;
    __syncthreads();
    float m8 = smx[0];
#pragma unroll
    for (int i = 1; i < 8; i++) m8 = fmaxf(m8, smx[i]);

    float e[8], sum = 0.f;
#pragma unroll
    for (int u = 0; u < 8; u++) { e[u] = __expf(v[u] - m8); sum += e[u]; }
#pragma unroll
    for (int off = 16; off; off >>= 1) sum += __shfl_xor_sync(0xffffffffu, sum, off);
    if (lid == 0) ssm[wid] = sum;
    __syncthreads();
    float tot = 0.f;
#pragma unroll
    for (int i = 0; i < 8; i++) tot += ssm[i];
    const float inv = 1.f / tot;
#pragma unroll
    for (int u = 0; u < 8; u++) Pp[t + (u << 8)] = __float2half(e[u] * inv);
}

// ============ LayerNorm ============
__global__ void __launch_bounds__(256) ln_kernel(const float* __restrict__ gamma,
                                                 const float* __restrict__ beta,
                                                 float* __restrict__ out) {
    const int row = blockIdx.x;
    const float* x = g_tmp + (size_t)row * DM;
    float s = 0.f, ss = 0.f;
#pragma unroll
    for (int u = 0; u < 4; u++) {
        float v = x[threadIdx.x + u * 256];
        s += v; ss += v * v;
    }
#pragma unroll
    for (int off = 16; off; off >>= 1) {
        s += __shfl_xor_sync(0xffffffffu, s, off);
        ss += __shfl_xor_sync(0xffffffffu, ss, off);
    }
    __shared__ float sm_s[8], sm_ss[8];
    int wid = threadIdx.x >> 5, lid = threadIdx.x & 31;
    if (lid == 0) { sm_s[wid] = s; sm_ss[wid] = ss; }
    __syncthreads();
    if (threadIdx.x == 0) {
        float a = 0.f, b2 = 0.f;
#pragma unroll
        for (int i2 = 0; i2 < 8; i2++) { a += sm_s[i2]; b2 += sm_ss[i2]; }
        sm_s[0] = a; sm_ss[0] = b2;
    }
    __syncthreads();
    const float mu = sm_s[0] * (1.f / DM);
    const float var = sm_ss[0] * (1.f / DM) - mu * mu;
    const float inv = rsqrtf(var + 1e-5f);
#pragma unroll
    for (int u = 0; u < 4; u++) {
        int c = threadIdx.x + u * 256;
        out[(size_t)row * DM + c] = (x[c] - mu) * inv * gamma[c] + beta[c];
    }
}

// ============ launch ============
extern "C" void kernel_launch(void* const* d_in, const int* in_sizes, int n_in,
                              void* d_out, int out_size) {
    const float* w       = (const float*)d_in[0];   // [1024,4,1024]
    const float* r       = (const float*)d_in[1];   // [2048,1024]
    const float* mems    = (const float*)d_in[2];   // [1024,4,1024]
    // d_in[3] = attn_mask (unused; mask computed analytically: j > i + MLEN)
    const float* qkv_w   = (const float*)d_in[4];   // [3072,1024]
    const float* r_net_w = (const float*)d_in[5];   // [1024,1024]
    const float* o_w     = (const float*)d_in[6];   // [1024,1024]
    const float* rr_bias = (const float*)d_in[7];   // [16,64]
    const float* rw_bias = (const float*)d_in[8];   // [16,64]
    const float* ln_g    = (const float*)d_in[9];   // [1024]
    const float* ln_b    = (const float*)d_in[10];  // [1024]
    float* out = (float*)d_out;

    // fp32 -> fp16
    conv_kernel<0><<<4096, 256>>>(mems, 1048576);
    conv_kernel<1><<<4096, 256>>>(w, 1048576);
    conv_kernel<2><<<3072, 256>>>(qkv_w, 786432);
    conv_kernel<3><<<2048, 256>>>(r, 524288);
    conv_kernel<4><<<1024, 256>>>(r_net_w, 262144);
    conv_kernel<5><<<1024, 256>>>(o_w, 262144);

    gemm_mma<0><<<dim3(24, 64), 256>>>(rw_bias);        // QKV proj + scatter
    gemm_mma<1><<<dim3(8, 16), 256>>>(nullptr);         // R proj
    brr_kernel<<<NH * KL / 256, 256>>>(rr_bias, rw_bias);
    gemm_mma<3><<<dim3(16, 8, 64), 256>>>(nullptr);     // T = Qw @ R^T (batched)
    gemm_mma<4><<<dim3(16, 8, 64), 256>>>(nullptr);     // S = AC + gather(T) + brr, mask
    softmax_kernel<<<64 * QL, 256>>>();                 // S -> P
    gemm_mma<5><<<dim3(1, 8, 64), 256>>>(nullptr);      // attn_vec = P @ V
    gemm_mma<2><<<dim3(8, 32), 256>>>(w);               // O proj + residual
    ln_kernel<<<4096, 256>>>(ln_g, ln_b, out);
}

// round 7
// speedup vs baseline: 5.5205x; 1.4978x over previous
#include <cuda_runtime.h>
#include <cuda_fp16.h>
#include <math.h>
#include <cstdint>

// ---------------- problem constants ----------------
constexpr int NH = 16, DH = 64, DM = 1024;
constexpr int QL = 1024, ML = 1024, KL = 2048, BS = 4;

// ---------------- scratch (device globals; no allocation) ----------------
__device__ __half g_Ah [(size_t)8192 * 1024];   // fp16 cat rows (m = k2*4+b)
__device__ __half g_W3h[(size_t)3072 * 1024];   // fp16 qkv_w
__device__ __half g_Ph [(size_t)2048 * 1024];   // fp16 r input
__device__ __half g_Wrh[(size_t)1024 * 1024];   // fp16 r_net_w
__device__ __half g_Woh[(size_t)1024 * 1024];   // fp16 o_w
__device__ __half g_Qwh[(size_t)BS * NH * QL * DH];  // (q+rw_bias)*0.125  [b*16+n][i][d]
__device__ __half g_Kh [(size_t)BS * NH * KL * DH];  // [b*16+n][j][d]
__device__ __half g_Vt [(size_t)BS * NH * DH * KL];  // [b*16+n][d][j]  (transposed)
__device__ __half g_Rh [(size_t)NH * KL * DH];       // [n][rel][d]
__device__ __half g_Th [(size_t)64 * QL * KL];       // T[z][i][rel] = Qw_i.R_rel + brr
__device__ __half g_avh[(size_t)QL * BS * DM];       // attn_vec rows m = i*4+b
__device__ float  g_tmp[(size_t)QL * BS * DM];       // w + attn_out (pre-LN)
__device__ float  g_brr[NH * KL];                    // (rr-rw)*0.125 . R[n][rel]

// ---------------- PTX helpers ----------------
__device__ __forceinline__ uint32_t smem_u32(const void* p) {
    uint32_t a;
    asm("{ .reg .u64 t; cvta.to.shared.u64 t, %1; cvt.u32.u64 %0, t; }" : "=r"(a) : "l"(p));
    return a;
}
__device__ __forceinline__ void ldsm_x4(uint32_t& r0, uint32_t& r1, uint32_t& r2, uint32_t& r3,
                                        uint32_t addr) {
    asm volatile("ldmatrix.sync.aligned.m8n8.x4.shared.b16 {%0,%1,%2,%3}, [%4];"
                 : "=r"(r0), "=r"(r1), "=r"(r2), "=r"(r3) : "r"(addr));
}
__device__ __forceinline__ void mma16816(float* d, const uint32_t* a, const uint32_t* b) {
    asm volatile("mma.sync.aligned.m16n8k16.row.col.f32.f16.f16.f32 "
                 "{%0,%1,%2,%3}, {%4,%5,%6,%7}, {%8,%9}, {%0,%1,%2,%3};"
                 : "+f"(d[0]), "+f"(d[1]), "+f"(d[2]), "+f"(d[3])
                 : "r"(a[0]), "r"(a[1]), "r"(a[2]), "r"(a[3]), "r"(b[0]), "r"(b[1]));
}
__device__ __forceinline__ uint32_t pack_h2(float x, float y) {
    __half2 h = __floats2half2_rn(x, y);
    return *(uint32_t*)&h;
}

// ============ fp32 -> fp16 conversion (SEL picks destination global) ============
template <int SEL>
__global__ void __launch_bounds__(256) conv_kernel(const float* __restrict__ src, int n4) {
    int i = blockIdx.x * 256 + threadIdx.x;
    if (i >= n4) return;
    __half* dst = (SEL == 0) ? g_Ah
                : (SEL == 1) ? g_Ah + (size_t)4096 * 1024
                : (SEL == 2) ? g_W3h
                : (SEL == 3) ? g_Ph
                : (SEL == 4) ? g_Wrh : g_Woh;
    float4 v = ((const float4*)src)[i];
    __half2* d2 = (__half2*)dst;
    d2[2 * i]     = __floats2half2_rn(v.x, v.y);
    d2[2 * i + 1] = __floats2half2_rn(v.z, v.w);
}

// ============ generic warp-tiled HMMA GEMM, D = A @ B^T (both k-major fp16) ============
// MODE 0: qkv   M=8192 N=3072 K=1024  -> scatter Qwh/Kh/Vt     (aux = rw_bias)
// MODE 1: r     M=2048 N=1024 K=1024  -> scatter Rh
// MODE 2: o     M=4096 N=1024 K=1024  -> g_tmp = D + aux(=w)
// MODE 3: T     M=1024 N=2048 K=64    batched z=64, +brr, fp16 out
template <int MODE>
__global__ void __launch_bounds__(256) gemm_mma(const float* __restrict__ aux) {
    constexpr int K  = (MODE <= 2) ? 1024 : 64;
    constexpr int BN = 128;
    constexpr int WARPS_M = 2;
    constexpr int WM = 64, WN = 32, MT = 4, NT = 4;
    constexpr int LDS = 40;
    constexpr int KC = K / 32;

    if constexpr (MODE == 3) {
        if (blockIdx.x + blockIdx.y < 7) return;   // dead T tiles (never read)
    }

    __shared__ __align__(16) __half As[2][128 * LDS];
    __shared__ __align__(16) __half Bs[2][BN * LDS];

    const int t = threadIdx.x, lane = t & 31, wid = t >> 5;
    const int wy = wid % WARPS_M, wx = wid / WARPS_M;
    const int bm = blockIdx.y * 128, bn = blockIdx.x * BN;
    const int z = blockIdx.z;

    const __half* Ab;
    const __half* Bb;
    if constexpr (MODE == 0)      { Ab = g_Ah;  Bb = g_W3h; }
    else if constexpr (MODE == 1) { Ab = g_Ph;  Bb = g_Wrh; }
    else if constexpr (MODE == 2) { Ab = g_avh; Bb = g_Woh; }
    else { Ab = g_Qwh + (size_t)z * QL * DH; Bb = g_Rh + (size_t)(z & 15) * KL * DH; }

    const int lrow = t >> 2, lc = (t & 3) * 8;
    const __half* aS0 = Ab + (size_t)(bm + lrow) * K + lc;
    const __half* aS1 = Ab + (size_t)(bm + lrow + 64) * K + lc;
    const __half* bS0 = Bb + (size_t)(bn + lrow) * K + lc;
    const __half* bS1 = Bb + (size_t)(bn + lrow + 64) * K + lc;
    const int sA0 = lrow * LDS + lc, sA1 = (lrow + 64) * LDS + lc;

    *(uint4*)&As[0][sA0] = *(const uint4*)aS0;
    *(uint4*)&As[0][sA1] = *(const uint4*)aS1;
    *(uint4*)&Bs[0][sA0] = *(const uint4*)bS0;
    *(uint4*)&Bs[0][sA1] = *(const uint4*)bS1;
    __syncthreads();

    float D[MT][NT][4];
#pragma unroll
    for (int mt = 0; mt < MT; mt++)
#pragma unroll
        for (int nt = 0; nt < NT; nt++)
#pragma unroll
            for (int r = 0; r < 4; r++) D[mt][nt][r] = 0.f;

    for (int kc = 0; kc < KC; kc++) {
        const int cur = kc & 1;
        uint4 pa0 = {}, pa1 = {}, pb0 = {}, pb1 = {};
        const bool pf = (kc + 1 < KC);
        if (pf) {
            pa0 = *(const uint4*)(aS0 + (kc + 1) * 32);
            pa1 = *(const uint4*)(aS1 + (kc + 1) * 32);
            pb0 = *(const uint4*)(bS0 + (kc + 1) * 32);
            pb1 = *(const uint4*)(bS1 + (kc + 1) * 32);
        }
        const uint32_t smA = smem_u32(&As[cur][0]);
        const uint32_t smB = smem_u32(&Bs[cur][0]);
#pragma unroll
        for (int ks = 0; ks < 2; ks++) {
            uint32_t af[MT][4], bf[NT][2];
#pragma unroll
            for (int mt = 0; mt < MT; mt++) {
                uint32_t a = smA + 2 * ((wy * WM + mt * 16 + (lane & 15)) * LDS
                                        + ks * 16 + (lane >> 4) * 8);
                ldsm_x4(af[mt][0], af[mt][1], af[mt][2], af[mt][3], a);
            }
#pragma unroll
            for (int np = 0; np < NT / 2; np++) {
                uint32_t a = smB + 2 * ((wx * WN + np * 16 + (lane & 7) + ((lane >> 4) << 3)) * LDS
                                        + ks * 16 + ((lane >> 3) & 1) * 8);
                ldsm_x4(bf[2 * np][0], bf[2 * np][1], bf[2 * np + 1][0], bf[2 * np + 1][1], a);
            }
#pragma unroll
            for (int mt = 0; mt < MT; mt++)
#pragma unroll
                for (int nt = 0; nt < NT; nt++)
                    mma16816(D[mt][nt], af[mt], bf[nt]);
        }
        if (pf) {
            *(uint4*)&As[1 - cur][sA0] = pa0;
            *(uint4*)&As[1 - cur][sA1] = pa1;
            *(uint4*)&Bs[1 - cur][sA0] = pb0;
            *(uint4*)&Bs[1 - cur][sA1] = pb1;
            __syncthreads();
        }
    }

#pragma unroll
    for (int mt = 0; mt < MT; mt++) {
#pragma unroll
        for (int nt = 0; nt < NT; nt++) {
#pragma unroll
            for (int r = 0; r < 4; r++) {
                const int row = bm + wy * WM + mt * 16 + (lane >> 2) + ((r >> 1) << 3);
                const int col = bn + wx * WN + nt * 8 + ((lane & 3) << 1) + (r & 1);
                const float v = D[mt][nt][r];
                if constexpr (MODE == 0) {
                    const int k2 = row >> 2, b = row & 3;
                    const int region = col >> 10, oo = col & 1023;
                    const int n = oo >> 6, d = oo & 63;
                    if (region == 0) {
                        if (k2 >= ML)
                            g_Qwh[(((size_t)(b * NH + n)) * QL + (k2 - ML)) * DH + d] =
                                __float2half((v + aux[oo]) * 0.125f);
                    } else if (region == 1) {
                        g_Kh[(((size_t)(b * NH + n)) * KL + k2) * DH + d] = __float2half(v);
                    } else {
                        g_Vt[(((size_t)(b * NH + n)) * DH + d) * KL + k2] = __float2half(v);
                    }
                } else if constexpr (MODE == 1) {
                    g_Rh[(((size_t)(col >> 6)) * KL + row) * DH + (col & 63)] = __float2half(v);
                } else if constexpr (MODE == 2) {
                    g_tmp[(size_t)row * DM + col] = v + aux[(size_t)row * DM + col];
                } else {
                    g_Th[((size_t)z * QL + row) * KL + col] =
                        __float2half(v + g_brr[(z & 15) * KL + col]);
                }
            }
        }
    }
}

// ============ brr[n][rel] = ((rr-rw)*0.125) . R[n][rel] ============
__global__ void __launch_bounds__(256) brr_kernel(const float* __restrict__ rr_bias,
                                                  const float* __restrict__ rw_bias) {
    int idx = blockIdx.x * 256 + threadIdx.x;
    int n = idx >> 11, rel = idx & (KL - 1);
    const __half* Rp = g_Rh + ((size_t)n * KL + rel) * DH;
    float acc = 0.f;
#pragma unroll
    for (int c = 0; c < DH; c++)
        acc = fmaf((rr_bias[n * DH + c] - rw_bias[n * DH + c]) * 0.125f,
                   __half2float(Rp[c]), acc);
    g_brr[idx] = acc;
}

// ============ flash attention: S = Q.K^T + gather(T), online softmax, O = P.V ============
constexpr int KSTR = 72;   // Ks row stride in halves (64 data + 8 pad; 16B-aligned rows)

__global__ void __launch_bounds__(256) flash_kernel() {
    __shared__ __align__(16) __half Ks[128 * KSTR];
    __shared__ __align__(16) __half Vs[64 * 136];

    const int t = threadIdx.x, lane = t & 31, wid = t >> 5;
    const int i0 = blockIdx.x * 128, z = blockIdx.y;
    const int b = z >> 4, n = z & 15;

    const __half* Qb = g_Qwh + (size_t)z * QL * DH;
    const __half* Kb = g_Kh + (size_t)z * KL * DH;
    const __half* Vb = g_Vt + (size_t)z * DH * KL;
    const __half* Tb = g_Th + (size_t)z * QL * KL;

    // load Q tile -> Ks (full coverage: 1024 uint4), extract A-frags
#pragma unroll
    for (int u = 0; u < 4; u++) {
        int idx = t + u * 256;
        int row = idx >> 3, c = (idx & 7) * 8;
        *(uint4*)&Ks[row * KSTR + c] = *(const uint4*)(Qb + (size_t)(i0 + row) * DH + c);
    }
    __syncthreads();
    uint32_t qf[4][4];
    {
        uint32_t smA = smem_u32(Ks);
#pragma unroll
        for (int ks = 0; ks < 4; ks++) {
            uint32_t a = smA + 2 * ((wid * 16 + (lane & 15)) * KSTR + ks * 16 + (lane >> 4) * 8);
            ldsm_x4(qf[ks][0], qf[ks][1], qf[ks][2], qf[ks][3], a);
        }
    }

    float O[8][4];
#pragma unroll
    for (int i = 0; i < 8; i++)
#pragma unroll
        for (int r = 0; r < 4; r++) O[i][r] = 0.f;
    float m0 = -1e30f, m1 = -1e30f, l0 = 0.f, l1 = 0.f;

    const int rbase = i0 + wid * 16 + (lane >> 2);      // row of d0/d1; d2/d3 at rbase+8
    const __half* Tr0 = Tb + (size_t)rbase * KL + (1023 - rbase);
    const __half* Tr1 = Tb + (size_t)(rbase + 8) * KL + (1023 - rbase - 8);
    const int njt = blockIdx.x + 9;

    for (int jt = 0; jt < njt; jt++) {
        const int j0 = jt * 128;
        __syncthreads();
        // K tile: 128 rows x 64 halves (1024 uint4); V tile: 64 rows x 128 halves (1024 uint4)
#pragma unroll
        for (int u = 0; u < 4; u++) {
            int idx = t + u * 256;
            { int row = idx >> 3, c = (idx & 7) * 8;
              *(uint4*)&Ks[row * KSTR + c] = *(const uint4*)(Kb + (size_t)(j0 + row) * DH + c); }
            { int row = idx >> 4, c = (idx & 15) * 8;
              *(uint4*)&Vs[row * 136 + c] = *(const uint4*)(Vb + (size_t)row * KL + j0 + c); }
        }
        __syncthreads();

        float S[16][4];
#pragma unroll
        for (int nt = 0; nt < 16; nt++)
#pragma unroll
            for (int r = 0; r < 4; r++) S[nt][r] = 0.f;

        const uint32_t smB = smem_u32(Ks);
#pragma unroll
        for (int ks = 0; ks < 4; ks++) {
            uint32_t bf[8][4];
#pragma unroll
            for (int np = 0; np < 8; np++) {
                uint32_t a = smB + 2 * ((np * 16 + (lane & 7) + ((lane >> 4) << 3)) * KSTR
                                        + ks * 16 + ((lane >> 3) & 1) * 8);
                ldsm_x4(bf[np][0], bf[np][1], bf[np][2], bf[np][3], a);
            }
#pragma unroll
            for (int nt = 0; nt < 16; nt++) {
                uint32_t bb[2] = {bf[nt >> 1][(nt & 1) * 2], bf[nt >> 1][(nt & 1) * 2 + 1]};
                mma16816(S[nt], qf[ks], bb);
            }
        }

        // add gathered T (contains brr); apply causal mask
        const int cb = j0 + (lane & 3) * 2;
        const bool partial = (j0 + 127 > i0 + ML);
        if (!partial) {
#pragma unroll
            for (int nt = 0; nt < 16; nt++) {
                int c0 = cb + nt * 8;
                S[nt][0] += __half2float(Tr0[c0]);
                S[nt][1] += __half2float(Tr0[c0 + 1]);
                S[nt][2] += __half2float(Tr1[c0]);
                S[nt][3] += __half2float(Tr1[c0 + 1]);
            }
        } else {
#pragma unroll
            for (int nt = 0; nt < 16; nt++) {
                int c0 = cb + nt * 8;
                S[nt][0] = (c0     <= rbase + ML)     ? S[nt][0] + __half2float(Tr0[c0])     : -1e30f;
                S[nt][1] = (c0 + 1 <= rbase + ML)     ? S[nt][1] + __half2float(Tr0[c0 + 1]) : -1e30f;
                S[nt][2] = (c0     <= rbase + 8 + ML) ? S[nt][2] + __half2float(Tr1[c0])     : -1e30f;
                S[nt][3] = (c0 + 1 <= rbase + 8 + ML) ? S[nt][3] + __half2float(Tr1[c0 + 1]) : -1e30f;
            }
        }

        // online softmax
        float mx0 = -1e30f, mx1 = -1e30f;
#pragma unroll
        for (int nt = 0; nt < 16; nt++) {
            mx0 = fmaxf(mx0, fmaxf(S[nt][0], S[nt][1]));
            mx1 = fmaxf(mx1, fmaxf(S[nt][2], S[nt][3]));
        }
        mx0 = fmaxf(mx0, __shfl_xor_sync(0xffffffffu, mx0, 1));
        mx0 = fmaxf(mx0, __shfl_xor_sync(0xffffffffu, mx0, 2));
        mx1 = fmaxf(mx1, __shfl_xor_sync(0xffffffffu, mx1, 1));
        mx1 = fmaxf(mx1, __shfl_xor_sync(0xffffffffu, mx1, 2));
        const float mn0 = fmaxf(m0, mx0), mn1 = fmaxf(m1, mx1);
        const float cr0 = __expf(m0 - mn0), cr1 = __expf(m1 - mn1);
        l0 *= cr0; l1 *= cr1;
#pragma unroll
        for (int i = 0; i < 8; i++) {
            O[i][0] *= cr0; O[i][1] *= cr0; O[i][2] *= cr1; O[i][3] *= cr1;
        }
#pragma unroll
        for (int nt = 0; nt < 16; nt++) {
            S[nt][0] = __expf(S[nt][0] - mn0);
            S[nt][1] = __expf(S[nt][1] - mn0);
            S[nt][2] = __expf(S[nt][2] - mn1);
            S[nt][3] = __expf(S[nt][3] - mn1);
            l0 += S[nt][0] + S[nt][1];
            l1 += S[nt][2] + S[nt][3];
        }
        m0 = mn0; m1 = mn1;

        // P @ V  (A-frags repacked from S registers; V B-frags from smem)
        const uint32_t smV = smem_u32(Vs);
#pragma unroll
        for (int kp = 0; kp < 8; kp++) {
            uint32_t af[4];
            af[0] = pack_h2(S[2 * kp][0],     S[2 * kp][1]);
            af[1] = pack_h2(S[2 * kp][2],     S[2 * kp][3]);
            af[2] = pack_h2(S[2 * kp + 1][0], S[2 * kp + 1][1]);
            af[3] = pack_h2(S[2 * kp + 1][2], S[2 * kp + 1][3]);
            uint32_t vf[4][4];
#pragma unroll
            for (int np = 0; np < 4; np++) {
                uint32_t a = smV + 2 * ((np * 16 + (lane & 7) + ((lane >> 4) << 3)) * 136
                                        + kp * 16 + ((lane >> 3) & 1) * 8);
                ldsm_x4(vf[np][0], vf[np][1], vf[np][2], vf[np][3], a);
            }
#pragma unroll
            for (int nt2 = 0; nt2 < 8; nt2++) {
                uint32_t bb[2] = {vf[nt2 >> 1][(nt2 & 1) * 2], vf[nt2 >> 1][(nt2 & 1) * 2 + 1]};
                mma16816(O[nt2], af, bb);
            }
        }
    }

    // finalize: reduce l over the 4 lanes sharing each row, scale, store fp16
    l0 += __shfl_xor_sync(0xffffffffu, l0, 1);
    l0 += __shfl_xor_sync(0xffffffffu, l0, 2);
    l1 += __shfl_xor_sync(0xffffffffu, l1, 1);
    l1 += __shfl_xor_sync(0xffffffffu, l1, 2);
    const float inv0 = 1.f / l0, inv1 = 1.f / l1;
    __half2* W0 = (__half2*)(g_avh + ((size_t)rbase * BS + b) * DM + n * DH);
    __half2* W1 = (__half2*)(g_avh + ((size_t)(rbase + 8) * BS + b) * DM + n * DH);
    const int cd = lane & 3;
#pragma unroll
    for (int nt2 = 0; nt2 < 8; nt2++) {
        W0[nt2 * 4 + cd] = __floats2half2_rn(O[nt2][0] * inv0, O[nt2][1] * inv0);
        W1[nt2 * 4 + cd] = __floats2half2_rn(O[nt2][2] * inv1, O[nt2][3] * inv1);
    }
}

// ============ LayerNorm ============
__global__ void __launch_bounds__(256) ln_kernel(const float* __restrict__ gamma,
                                                 const float* __restrict__ beta,
                                                 float* __restrict__ out) {
    const int row = blockIdx.x;
    const float* x = g_tmp + (size_t)row * DM;
    float s = 0.f, ss = 0.f;
#pragma unroll
    for (int u = 0; u < 4; u++) {
        float v = x[threadIdx.x + u * 256];
        s += v; ss += v * v;
    }
#pragma unroll
    for (int off = 16; off; off >>= 1) {
        s += __shfl_xor_sync(0xffffffffu, s, off);
        ss += __shfl_xor_sync(0xffffffffu, ss, off);
    }
    __shared__ float sm_s[8], sm_ss[8];
    int wid = threadIdx.x >> 5, lid = threadIdx.x & 31;
    if (lid == 0) { sm_s[wid] = s; sm_ss[wid] = ss; }
    __syncthreads();
    if (threadIdx.x == 0) {
        float a = 0.f, b2 = 0.f;
#pragma unroll
        for (int i2 = 0; i2 < 8; i2++) { a += sm_s[i2]; b2 += sm_ss[i2]; }
        sm_s[0] = a; sm_ss[0] = b2;
    }
    __syncthreads();
    const float mu = sm_s[0] * (1.f / DM);
    const float var = sm_ss[0] * (1.f / DM) - mu * mu;
    const float inv = rsqrtf(var + 1e-5f);
#pragma unroll
    for (int u = 0; u < 4; u++) {
        int c = threadIdx.x + u * 256;
        out[(size_t)row * DM + c] = (x[c] - mu) * inv * gamma[c] + beta[c];
    }
}

// ============ launch ============
extern "C" void kernel_launch(void* const* d_in, const int* in_sizes, int n_in,
                              void* d_out, int out_size) {
    const float* w       = (const float*)d_in[0];   // [1024,4,1024]
    const float* r       = (const float*)d_in[1];   // [2048,1024]
    const float* mems    = (const float*)d_in[2];   // [1024,4,1024]
    // d_in[3] = attn_mask (unused; mask computed analytically: j > i + MLEN)
    const float* qkv_w   = (const float*)d_in[4];   // [3072,1024]
    const float* r_net_w = (const float*)d_in[5];   // [1024,1024]
    const float* o_w     = (const float*)d_in[6];   // [1024,1024]
    const float* rr_bias = (const float*)d_in[7];   // [16,64]
    const float* rw_bias = (const float*)d_in[8];   // [16,64]
    const float* ln_g    = (const float*)d_in[9];   // [1024]
    const float* ln_b    = (const float*)d_in[10];  // [1024]
    float* out = (float*)d_out;

    conv_kernel<0><<<4096, 256>>>(mems, 1048576);
    conv_kernel<1><<<4096, 256>>>(w, 1048576);
    conv_kernel<2><<<3072, 256>>>(qkv_w, 786432);
    conv_kernel<3><<<2048, 256>>>(r, 524288);
    conv_kernel<4><<<1024, 256>>>(r_net_w, 262144);
    conv_kernel<5><<<1024, 256>>>(o_w, 262144);

    gemm_mma<0><<<dim3(24, 64), 256>>>(rw_bias);        // QKV proj + scatter
    gemm_mma<1><<<dim3(8, 16), 256>>>(nullptr);         // R proj
    brr_kernel<<<NH * KL / 256, 256>>>(rr_bias, rw_bias);
    gemm_mma<3><<<dim3(16, 8, 64), 256>>>(nullptr);     // T = Qw @ R^T + brr (fp16)
    flash_kernel<<<dim3(8, 64), 256>>>();               // fused S/softmax/PV
    gemm_mma<2><<<dim3(8, 32), 256>>>(w);               // O proj + residual
    ln_kernel<<<4096, 256>>>(ln_g, ln_b, out);
}